// round 14
// baseline (speedup 1.0000x reference)
#include <cuda_runtime.h>
#include <cuda_bf16.h>

// Problem constants (fixed by setup_inputs)
#define BB 8
#define DD 32
#define NN 131072
#define KK 64
#define DP 33            // padded row for means in pass3
#define G1X 64           // pass1 grid.x; one accumulator replica PER BLOCK
#define IGNORE_IDX (-100)
#define DELTA_V 0.5f
#define DELTA_D 1.5f

#define SUMSZ (G1X * BB * KK * DD)   // 1M floats = 4 MiB, L2-resident

// ---- scratch (allocation-free: __device__ globals) ----
__device__ float g_sum [SUMSZ];          // per-(block,batch) segment sums
__device__ float g_cnt[BB * KK];
__device__ float g_mu [BB * KK * DD];
__device__ float g_var[BB * KK];
__device__ float g_np  [BB];             // number of present clusters
__device__ float g_ldist[BB];            // ldist numerator (sum of hinges)
__device__ float g_lreg [BB];            // lreg numerator

// fire-and-forget vector reduction to global (REDG, no return value)
__device__ __forceinline__ void red_add_v4(float* p, float a, float b2, float c, float d) {
    asm volatile("red.global.add.v4.f32 [%0], {%1, %2, %3, %4};"
                 :: "l"(p), "f"(a), "f"(b2), "f"(c), "f"(d) : "memory");
}

// ---------------------------------------------------------------------------
__global__ void k_zero() {
    int t = blockIdx.x * blockDim.x + threadIdx.x;
    if (t < SUMSZ / 4) ((float4*)g_sum)[t] = make_float4(0.f, 0.f, 0.f, 0.f);
    if (t < BB * KK) { g_cnt[t] = 0.0f; g_var[t] = 0.0f; }
    if (t < BB) { g_np[t] = 0.0f; g_ldist[t] = 0.0f; g_lreg[t] = 0.0f; }
}

// ---------------------------------------------------------------------------
// Pass 1 (v7): REGISTER-STAGED loads, then scatter.
// Key fix vs v5/v6: all 16 LDG.64 of a half-batch issue back-to-back with no
// consumer in between (REDGs only after), restoring pass3-like MLP (~16).
// Scatter: REDG.v4 into per-block replica (no cross-CTA address contention).
// grid = (G1X, BB), block = 256.
__global__ void __launch_bounds__(256) k_pass1(const float* __restrict__ emb,
                                               const int*   __restrict__ cls,
                                               const int*   __restrict__ inst) {
    __shared__ float s_cnt[KK];
    const int b   = blockIdx.y;
    const int tid = threadIdx.x;

    if (tid < KK) s_cnt[tid] = 0.0f;
    __syncthreads();

    float* gsum = g_sum + (size_t)(blockIdx.x * BB + b) * KK * DD;

    const float* eb = emb  + (size_t)b * DD * NN;
    const int*   cb = cls  + (size_t)b * NN;
    const int*   ib = inst + (size_t)b * NN;

    const int stride2 = gridDim.x * blockDim.x;        // 16384
    for (int n2 = blockIdx.x * blockDim.x + tid; n2 < NN / 2; n2 += stride2) {
        int2 c2 = ((const int2*)cb)[n2];
        int2 i2 = ((const int2*)ib)[n2];
        int id0 = (c2.x == IGNORE_IDX) ? -1 : ((c2.x == 1) ? 0 : i2.x);
        int id1 = (c2.y == IGNORE_IDX) ? -1 : ((c2.y == 1) ? 0 : i2.y);
        if (id0 >= 0) atomicAdd(&s_cnt[id0], 1.0f);
        if (id1 >= 0) atomicAdd(&s_cnt[id1], 1.0f);

        float* r0 = gsum + (id0 < 0 ? 0 : id0) * DD;
        float* r1 = gsum + (id1 < 0 ? 0 : id1) * DD;

        float2 v[16];
        // ---- half-batch 0: d = 0..15 (16 LDG.64, no consumer in between) --
        #pragma unroll
        for (int d = 0; d < 16; d++)
            v[d] = ((const float2*)(eb + (size_t)d * NN))[n2];
        if (id0 >= 0) {
            #pragma unroll
            for (int j = 0; j < 4; j++)
                red_add_v4(r0 + 4 * j, v[4*j].x, v[4*j+1].x, v[4*j+2].x, v[4*j+3].x);
        }
        if (id1 >= 0) {
            #pragma unroll
            for (int j = 0; j < 4; j++)
                red_add_v4(r1 + 4 * j, v[4*j].y, v[4*j+1].y, v[4*j+2].y, v[4*j+3].y);
        }
        // ---- half-batch 1: d = 16..31 ------------------------------------
        #pragma unroll
        for (int d = 0; d < 16; d++)
            v[d] = ((const float2*)(eb + (size_t)(16 + d) * NN))[n2];
        if (id0 >= 0) {
            #pragma unroll
            for (int j = 0; j < 4; j++)
                red_add_v4(r0 + 16 + 4 * j, v[4*j].x, v[4*j+1].x, v[4*j+2].x, v[4*j+3].x);
        }
        if (id1 >= 0) {
            #pragma unroll
            for (int j = 0; j < 4; j++)
                red_add_v4(r1 + 16 + 4 * j, v[4*j].y, v[4*j+1].y, v[4*j+2].y, v[4*j+3].y);
        }
    }
    __syncthreads();
    if (tid < KK) {
        float c = s_cnt[tid];
        if (c != 0.0f) atomicAdd(&g_cnt[b * KK + tid], c);
    }
}

// ---------------------------------------------------------------------------
// Reduce G1X per-block replicas AND compute means. t -> (b,k,d).
// grid = BB*KK*DD/256 = 64 blocks.
__global__ void k_reduce() {
    int t = blockIdx.x * blockDim.x + threadIdx.x;   // 0 .. BB*KK*DD-1
    float s = 0.0f;
    #pragma unroll 8
    for (int r = 0; r < G1X; r++)
        s += g_sum[(size_t)r * (BB * KK * DD) + t];
    int bk = t >> 5;                                 // b*KK + k
    g_mu[t] = s / (g_cnt[bk] + 1e-8f);
}

// ---------------------------------------------------------------------------
// Pass 2 (v2): ROW-PARALLEL pairwise. block (i, b) handles cluster-row i:
//  - all ordered pairs (i, j): thread t -> j = t>>2, quarter q = t&3 (8 d's),
//    4-lane shfl reduce -> hinge at lane q==0 -> smem acc -> one global atomic
//  - warp 0 afterwards: lreg_i + np_i contribution.
// grid = (KK, BB), block = 256 -> 512 blocks (was 8: 14.3us latency-bound).
__global__ void __launch_bounds__(256) k_pass2() {
    const int i   = blockIdx.x;
    const int b   = blockIdx.y;
    const int tid = threadIdx.x;
    __shared__ float s_mui[DD];
    __shared__ float s_pres[KK];
    __shared__ float s_ldist;

    const float* mub = g_mu + (size_t)b * KK * DD;
    if (tid < DD) s_mui[tid] = mub[i * DD + tid];
    if (tid < KK) s_pres[tid] = (g_cnt[b * KK + tid] > 0.0f) ? 1.0f : 0.0f;
    if (tid == 0) s_ldist = 0.0f;
    __syncthreads();

    const bool pres_i = (s_pres[i] > 0.0f);

    if (pres_i) {
        int j = tid >> 2;
        int q = tid & 3;
        float part = 0.0f;
        const float* mj = mub + j * DD + q * 8;
        const float* mi = s_mui + q * 8;
        #pragma unroll
        for (int u = 0; u < 8; u++)
            part += fabsf(mi[u] - mj[u]);
        part += __shfl_xor_sync(0xffffffffu, part, 1);
        part += __shfl_xor_sync(0xffffffffu, part, 2);
        if (q == 0 && j != i && s_pres[j] > 0.0f) {
            float h = fmaxf(2.0f * DELTA_D - part, 0.0f);
            atomicAdd(&s_ldist, h * h);
        }
    }
    __syncthreads();

    if (tid < 32) {
        // lreg_i + np_i (warp 0), ldist flush (lane 0)
        float a = pres_i ? fabsf(s_mui[tid]) : 0.0f;
        #pragma unroll
        for (int off = 16; off > 0; off >>= 1)
            a += __shfl_xor_sync(0xffffffffu, a, off);
        if (tid == 0) {
            float ld = s_ldist;
            if (ld != 0.0f) atomicAdd(&g_ldist[b], ld);
            if (pres_i) {
                atomicAdd(&g_lreg[b], a);
                atomicAdd(&g_np[b], 1.0f);
            }
        }
    }
}

// ---------------------------------------------------------------------------
// Pass 3 (anchor, best measured 28.1us / 68% DRAM): float2, 2 pts/thread.
__global__ void __launch_bounds__(256) k_pass3(const float* __restrict__ emb,
                                               const int*   __restrict__ cls,
                                               const int*   __restrict__ inst) {
    __shared__ float s_mu[KK * DP];
    __shared__ float s_var[KK];
    const int b = blockIdx.y;

    for (int i = threadIdx.x; i < KK * DD; i += blockDim.x) {
        int k = i / DD, d = i - k * DD;
        s_mu[k * DP + d] = g_mu[b * KK * DD + i];
    }
    if (threadIdx.x < KK) s_var[threadIdx.x] = 0.0f;
    __syncthreads();

    const float* eb = emb  + (size_t)b * DD * NN;
    const int*   cb = cls  + (size_t)b * NN;
    const int*   ib = inst + (size_t)b * NN;

    const int stride2 = gridDim.x * blockDim.x;
    for (int n2 = blockIdx.x * blockDim.x + threadIdx.x; n2 < NN / 2; n2 += stride2) {
        int2 c2 = ((const int2*)cb)[n2];
        int2 i2 = ((const int2*)ib)[n2];
        int id0 = (c2.x == IGNORE_IDX) ? -1 : ((c2.x == 1) ? 0 : i2.x);
        int id1 = (c2.y == IGNORE_IDX) ? -1 : ((c2.y == 1) ? 0 : i2.y);
        const float* m0 = &s_mu[(id0 < 0 ? 0 : id0) * DP];
        const float* m1 = &s_mu[(id1 < 0 ? 0 : id1) * DP];

        float a0 = 0.0f, a1 = 0.0f;
        #pragma unroll
        for (int d = 0; d < DD; d++) {
            float2 v = ((const float2*)(eb + (size_t)d * NN))[n2];
            a0 += fabsf(v.x - m0[d]);
            a1 += fabsf(v.y - m1[d]);
        }
        if (id0 >= 0) { float h = fmaxf(a0 - DELTA_V, 0.0f); atomicAdd(&s_var[id0], h * h); }
        if (id1 >= 0) { float h = fmaxf(a1 - DELTA_V, 0.0f); atomicAdd(&s_var[id1], h * h); }
    }
    __syncthreads();
    if (threadIdx.x < KK) {
        float v = s_var[threadIdx.x];
        if (v != 0.0f) atomicAdd(&g_var[b * KK + threadIdx.x], v);
    }
}

// ---------------------------------------------------------------------------
// Pass 4: finalize 4 output scalars (means over batch).
__global__ void k_pass4(float* __restrict__ out, int out_size) {
    __shared__ float acc[4];
    if (threadIdx.x < 4) acc[threadIdx.x] = 0.0f;
    __syncthreads();
    if (threadIdx.x < BB) {
        const int b = threadIdx.x;
        float lvar = 0.0f;
        for (int k = 0; k < KK; k++)
            lvar += g_var[b * KK + k] / (g_cnt[b * KK + k] + 1e-8f);
        float np     = g_np[b];
        float n_inst = fmaxf(np, 1.0f);
        float npairs = np * np - np;
        lvar /= n_inst;
        float lv = 1.0f * lvar;
        float ld = (npairs > 0.0f) ? g_ldist[b] / fmaxf(npairs, 1.0f) : 0.0f;
        float lr = 0.001f * (g_lreg[b] / n_inst);
        float loss = lv + ld + lr;
        atomicAdd(&acc[0], loss / BB);
        atomicAdd(&acc[1], lv   / BB);
        atomicAdd(&acc[2], ld   / BB);
        atomicAdd(&acc[3], lr   / BB);
    }
    __syncthreads();
    if (threadIdx.x < 4 && threadIdx.x < out_size)
        out[threadIdx.x] = acc[threadIdx.x];
}

// ---------------------------------------------------------------------------
extern "C" void kernel_launch(void* const* d_in, const int* in_sizes, int n_in,
                              void* d_out, int out_size) {
    const float* emb  = (const float*)d_in[0];
    const int*   cls  = (const int*)  d_in[1];
    const int*   inst = (const int*)  d_in[2];
    float* out = (float*)d_out;

    (void)in_sizes; (void)n_in;

    k_zero<<<(SUMSZ / 4 + 255) / 256, 256>>>();

    dim3 grid1(G1X, BB);
    k_pass1<<<grid1, 256>>>(emb, cls, inst);

    k_reduce<<<(BB * KK * DD) / 256, 256>>>();

    dim3 grid2(KK, BB);
    k_pass2<<<grid2, 256>>>();

    dim3 grid3(128, BB);
    k_pass3<<<grid3, 256>>>(emb, cls, inst);

    k_pass4<<<1, 64>>>(out, out_size);
}

// round 17
// speedup vs baseline: 1.2270x; 1.2270x over previous
#include <cuda_runtime.h>
#include <cuda_bf16.h>

// Problem constants (fixed by setup_inputs)
#define BB 8
#define DD 32
#define NN 131072
#define KK 64
#define DP 33            // padded row for means in pass3
#define NT 256           // points per chunk (== blockDim)
#define G1X 64           // pass1 grid.x; one accumulator replica PER BLOCK
#define IGNORE_IDX (-100)
#define DELTA_V 0.5f
#define DELTA_D 1.5f

#define SUMSZ (G1X * BB * KK * DD)   // 1M floats = 4 MiB, L2-resident

// ---- scratch (allocation-free: __device__ globals) ----
__device__ float g_sum [SUMSZ];          // per-(block,batch) segment sums
__device__ float g_cnt[BB * KK];
__device__ float g_mu [BB * KK * DD];
__device__ float g_var[BB * KK];
__device__ float g_np  [BB];
__device__ float g_ldist[BB];
__device__ float g_lreg [BB];

// fire-and-forget scalar reduction to global (REDG, no return value)
__device__ __forceinline__ void red_add_f32(float* p, float v) {
    asm volatile("red.global.add.f32 [%0], %1;" :: "l"(p), "f"(v) : "memory");
}

// ---------------------------------------------------------------------------
__global__ void k_zero() {
    int t = blockIdx.x * blockDim.x + threadIdx.x;
    if (t < SUMSZ / 4) ((float4*)g_sum)[t] = make_float4(0.f, 0.f, 0.f, 0.f);
    if (t < BB * KK) { g_cnt[t] = 0.0f; g_var[t] = 0.0f; }
    if (t < BB) { g_np[t] = 0.0f; g_ldist[t] = 0.0f; g_lreg[t] = 0.0f; }
}

// ---------------------------------------------------------------------------
// Pass 1 (v8): warp-per-point, COALESCED scatter.
// - stage [32 d][256 n] XOR-swizzled tile (proven v2/v4): float4 coalesced
//   fill, conflict-free transposed reads (lane = feature).
// - per point: broadcast LDS id + 1 conflict-free LDS + ONE coalesced
//   red.global.add.f32 (lane l -> gsum[id*32+l], 32 consecutive addrs =
//   1 wavefront/point vs 32 for the per-lane-divergent REDG.v4 of v5-v7).
//   REDG is fire-and-forget: no dependent read-back chain (v4's flaw).
// - replica per block -> no cross-CTA address contention (v6's fix, kept).
// - counts: 1 spread-address smem atomic per point at id-computation time.
// grid = (G1X, BB), block = 256.  8 chunks per block.
__global__ void __launch_bounds__(256) k_pass1(const float* __restrict__ emb,
                                               const int*   __restrict__ cls,
                                               const int*   __restrict__ inst) {
    __shared__ float s_tile[DD * 256];   // 32 KB
    __shared__ int   s_id[NT];
    __shared__ float s_cnt[KK];

    const int b    = blockIdx.y;
    const int tid  = threadIdx.x;
    const int w    = tid >> 5;
    const int lane = tid & 31;

    if (tid < KK) s_cnt[tid] = 0.0f;

    float* gsum = g_sum + (size_t)(blockIdx.x * BB + b) * KK * DD;

    const float* eb = emb  + (size_t)b * DD * NN;
    const int*   cb = cls  + (size_t)b * NN;
    const int*   ib = inst + (size_t)b * NN;

    const int chunk_stride = G1X * NT;   // 16384
    for (int n0 = blockIdx.x * NT; n0 < NN; n0 += chunk_stride) {
        __syncthreads();   // prev chunk readers done (covers s_cnt init)

        // ids + counts for this chunk (one point per thread)
        {
            int c  = cb[n0 + tid];
            int id = (c == IGNORE_IDX) ? -1 : ((c == 1) ? 0 : ib[n0 + tid]);
            s_id[tid] = id;
            if (id >= 0) atomicAdd(&s_cnt[id], 1.0f);
        }
        // fill tile: 8 float4 loads per thread, XOR-swizzled scalar stores
        #pragma unroll
        for (int r = 0; r < 8; r++) {
            int i  = r * 256 + tid;
            int d  = i >> 6;
            int n4 = i & 63;
            float4 v = ((const float4*)(eb + (size_t)d * NN + n0))[n4];
            int base = (d << 8);
            int nb   = n4 << 2;
            s_tile[base + ((nb + 0) ^ d)] = v.x;
            s_tile[base + ((nb + 1) ^ d)] = v.y;
            s_tile[base + ((nb + 2) ^ d)] = v.z;
            s_tile[base + ((nb + 3) ^ d)] = v.w;
        }
        __syncthreads();

        // warp w scatters points [w*32, w*32+32): 1 coalesced REDG per point
        #pragma unroll 8
        for (int p = 0; p < 32; p++) {
            int n  = (w << 5) + p;
            int id = s_id[n];                                  // broadcast LDS
            if (id >= 0) {                                     // warp-uniform
                float val = s_tile[(lane << 8) + (n ^ lane)];  // conflict-free
                red_add_f32(&gsum[(id << 5) + lane], val);     // coalesced
            }
        }
    }
    __syncthreads();
    if (tid < KK) {
        float c = s_cnt[tid];
        if (c != 0.0f) atomicAdd(&g_cnt[b * KK + tid], c);
    }
}

// ---------------------------------------------------------------------------
// Reduce G1X per-block replicas AND compute means. t -> (b,k,d).
__global__ void k_reduce() {
    int t = blockIdx.x * blockDim.x + threadIdx.x;   // 0 .. BB*KK*DD-1
    float s = 0.0f;
    #pragma unroll 8
    for (int r = 0; r < G1X; r++)
        s += g_sum[(size_t)r * (BB * KK * DD) + t];
    int bk = t >> 5;                                 // b*KK + k
    g_mu[t] = s / (g_cnt[bk] + 1e-8f);
}

// ---------------------------------------------------------------------------
// Pass 2 (row-parallel, measured 8.7us): block (i, b) handles cluster-row i.
__global__ void __launch_bounds__(256) k_pass2() {
    const int i   = blockIdx.x;
    const int b   = blockIdx.y;
    const int tid = threadIdx.x;
    __shared__ float s_mui[DD];
    __shared__ float s_pres[KK];
    __shared__ float s_ldist;

    const float* mub = g_mu + (size_t)b * KK * DD;
    if (tid < DD) s_mui[tid] = mub[i * DD + tid];
    if (tid < KK) s_pres[tid] = (g_cnt[b * KK + tid] > 0.0f) ? 1.0f : 0.0f;
    if (tid == 0) s_ldist = 0.0f;
    __syncthreads();

    const bool pres_i = (s_pres[i] > 0.0f);

    if (pres_i) {
        int j = tid >> 2;
        int q = tid & 3;
        float part = 0.0f;
        const float* mj = mub + j * DD + q * 8;
        const float* mi = s_mui + q * 8;
        #pragma unroll
        for (int u = 0; u < 8; u++)
            part += fabsf(mi[u] - mj[u]);
        part += __shfl_xor_sync(0xffffffffu, part, 1);
        part += __shfl_xor_sync(0xffffffffu, part, 2);
        if (q == 0 && j != i && s_pres[j] > 0.0f) {
            float h = fmaxf(2.0f * DELTA_D - part, 0.0f);
            atomicAdd(&s_ldist, h * h);
        }
    }
    __syncthreads();

    if (tid < 32) {
        float a = pres_i ? fabsf(s_mui[tid]) : 0.0f;
        #pragma unroll
        for (int off = 16; off > 0; off >>= 1)
            a += __shfl_xor_sync(0xffffffffu, a, off);
        if (tid == 0) {
            float ld = s_ldist;
            if (ld != 0.0f) atomicAdd(&g_ldist[b], ld);
            if (pres_i) {
                atomicAdd(&g_lreg[b], a);
                atomicAdd(&g_np[b], 1.0f);
            }
        }
    }
}

// ---------------------------------------------------------------------------
// Pass 3 (anchor, best measured 28.1us / 68% DRAM): float2, 2 pts/thread.
__global__ void __launch_bounds__(256) k_pass3(const float* __restrict__ emb,
                                               const int*   __restrict__ cls,
                                               const int*   __restrict__ inst) {
    __shared__ float s_mu[KK * DP];
    __shared__ float s_var[KK];
    const int b = blockIdx.y;

    for (int i = threadIdx.x; i < KK * DD; i += blockDim.x) {
        int k = i / DD, d = i - k * DD;
        s_mu[k * DP + d] = g_mu[b * KK * DD + i];
    }
    if (threadIdx.x < KK) s_var[threadIdx.x] = 0.0f;
    __syncthreads();

    const float* eb = emb  + (size_t)b * DD * NN;
    const int*   cb = cls  + (size_t)b * NN;
    const int*   ib = inst + (size_t)b * NN;

    const int stride2 = gridDim.x * blockDim.x;
    for (int n2 = blockIdx.x * blockDim.x + threadIdx.x; n2 < NN / 2; n2 += stride2) {
        int2 c2 = ((const int2*)cb)[n2];
        int2 i2 = ((const int2*)ib)[n2];
        int id0 = (c2.x == IGNORE_IDX) ? -1 : ((c2.x == 1) ? 0 : i2.x);
        int id1 = (c2.y == IGNORE_IDX) ? -1 : ((c2.y == 1) ? 0 : i2.y);
        const float* m0 = &s_mu[(id0 < 0 ? 0 : id0) * DP];
        const float* m1 = &s_mu[(id1 < 0 ? 0 : id1) * DP];

        float a0 = 0.0f, a1 = 0.0f;
        #pragma unroll
        for (int d = 0; d < DD; d++) {
            float2 v = ((const float2*)(eb + (size_t)d * NN))[n2];
            a0 += fabsf(v.x - m0[d]);
            a1 += fabsf(v.y - m1[d]);
        }
        if (id0 >= 0) { float h = fmaxf(a0 - DELTA_V, 0.0f); atomicAdd(&s_var[id0], h * h); }
        if (id1 >= 0) { float h = fmaxf(a1 - DELTA_V, 0.0f); atomicAdd(&s_var[id1], h * h); }
    }
    __syncthreads();
    if (threadIdx.x < KK) {
        float v = s_var[threadIdx.x];
        if (v != 0.0f) atomicAdd(&g_var[b * KK + threadIdx.x], v);
    }
}

// ---------------------------------------------------------------------------
// Pass 4: finalize 4 output scalars (means over batch).
__global__ void k_pass4(float* __restrict__ out, int out_size) {
    __shared__ float acc[4];
    if (threadIdx.x < 4) acc[threadIdx.x] = 0.0f;
    __syncthreads();
    if (threadIdx.x < BB) {
        const int b = threadIdx.x;
        float lvar = 0.0f;
        for (int k = 0; k < KK; k++)
            lvar += g_var[b * KK + k] / (g_cnt[b * KK + k] + 1e-8f);
        float np     = g_np[b];
        float n_inst = fmaxf(np, 1.0f);
        float npairs = np * np - np;
        lvar /= n_inst;
        float lv = 1.0f * lvar;
        float ld = (npairs > 0.0f) ? g_ldist[b] / fmaxf(npairs, 1.0f) : 0.0f;
        float lr = 0.001f * (g_lreg[b] / n_inst);
        float loss = lv + ld + lr;
        atomicAdd(&acc[0], loss / BB);
        atomicAdd(&acc[1], lv   / BB);
        atomicAdd(&acc[2], ld   / BB);
        atomicAdd(&acc[3], lr   / BB);
    }
    __syncthreads();
    if (threadIdx.x < 4 && threadIdx.x < out_size)
        out[threadIdx.x] = acc[threadIdx.x];
}

// ---------------------------------------------------------------------------
extern "C" void kernel_launch(void* const* d_in, const int* in_sizes, int n_in,
                              void* d_out, int out_size) {
    const float* emb  = (const float*)d_in[0];
    const int*   cls  = (const int*)  d_in[1];
    const int*   inst = (const int*)  d_in[2];
    float* out = (float*)d_out;

    (void)in_sizes; (void)n_in;

    k_zero<<<(SUMSZ / 4 + 255) / 256, 256>>>();

    dim3 grid1(G1X, BB);
    k_pass1<<<grid1, 256>>>(emb, cls, inst);

    k_reduce<<<(BB * KK * DD) / 256, 256>>>();

    dim3 grid2(KK, BB);
    k_pass2<<<grid2, 256>>>();

    dim3 grid3(128, BB);
    k_pass3<<<grid3, 256>>>(emb, cls, inst);

    k_pass4<<<1, 64>>>(out, out_size);
}